// round 10
// baseline (speedup 1.0000x reference)
#include <cuda_runtime.h>
#include <cuda_bf16.h>
#include <math.h>
#include <stdint.h>

#define BATCH 8
#define SEQ   2048
#define EMB   1024
#define HEAD  128
#define NTRI  136            // lower-tri 128x128 tiles per batch
#define SCALE 0.03125f       // 1/sqrt(1024)

typedef unsigned short ushort_t;

// Stage geometry (M-tile 64, N-tile 128, K-chunk 32):
//   A slabs: [64][40] ushort  = 5120B  (hi @0, lo @5120)
//   B slabs: [128][40] ushort = 10240B (hi @10240, lo @20480)
#define SLAB_A 5120u
#define SLAB_B 10240u
#define STAGE  30720u

// ---------------- global scratch: pre-split bf16 hi/lo arrays -------------------
__device__ ushort_t g_xh[BATCH * SEQ * EMB], g_xl[BATCH * SEQ * EMB];     // X split [row][emb]
__device__ ushort_t g_wth[3 * HEAD * EMB],   g_wtl[3 * HEAD * EMB];       // W^T split [mat][head][emb]
__device__ ushort_t g_qh[BATCH * SEQ * HEAD], g_ql[BATCH * SEQ * HEAD];   // q' split [tok][head]
__device__ ushort_t g_kh[BATCH * SEQ * HEAD], g_kl[BATCH * SEQ * HEAD];   // k  split [tok][head]
__device__ ushort_t g_vth[BATCH * HEAD * SEQ], g_vtl[BATCH * HEAD * SEQ]; // (v*inv)^T split [head][key]
__device__ ushort_t g_eh[(size_t)BATCH * SEQ * SEQ];                      // expS hi [q][key] 64MB
__device__ ushort_t g_el[(size_t)BATCH * SEQ * SEQ];                      // expS lo 64MB
__device__ float    g_v[BATCH * SEQ * HEAD];
__device__ float    g_colsum[BATCH * SEQ];

// ---------------- helpers ------------------------------------------------------
__device__ __forceinline__ uint32_t smem_u32(const void* p) {
    uint32_t a;
    asm("{ .reg .u64 t; cvta.to.shared.u64 t, %1; cvt.u32.u64 %0, t; }" : "=r"(a) : "l"(p));
    return a;
}
__device__ __forceinline__ void cpa16(uint32_t dst, const void* src) {
    asm volatile("cp.async.cg.shared.global [%0], [%1], 16;" :: "r"(dst), "l"(src));
}
__device__ __forceinline__ float fast_exp(float x) {
    float r = 2.0876757e-9f;
    r = fmaf(r, x, 2.5052108e-8f);
    r = fmaf(r, x, 2.7557319e-7f);
    r = fmaf(r, x, 2.7557319e-6f);
    r = fmaf(r, x, 2.4801587e-5f);
    r = fmaf(r, x, 1.9841270e-4f);
    r = fmaf(r, x, 1.3888889e-3f);
    r = fmaf(r, x, 8.3333333e-3f);
    r = fmaf(r, x, 4.1666667e-2f);
    r = fmaf(r, x, 1.6666667e-1f);
    r = fmaf(r, x, 0.5f);
    r = fmaf(r, x, 1.0f);
    r = fmaf(r, x, 1.0f);
    if (fabsf(x) > 2.0f) r = __expf(x);
    return r;
}
__device__ __forceinline__ void tri_decode(int t, int& qt, int& kt) {
    int q = (int)((sqrtf(8.0f * (float)t + 1.0f) - 1.0f) * 0.5f);
    while ((q + 1) * (q + 2) / 2 <= t) q++;
    while (q * (q + 1) / 2 > t) q--;
    qt = q;
    kt = t - q * (q + 1) / 2;
}
__device__ __forceinline__ void split2(float x, ushort_t& h, ushort_t& l) {
    __nv_bfloat16 bh = __float2bfloat16_rn(x);
    float r = x - __bfloat162float(bh);
    __nv_bfloat16 bl = __float2bfloat16_rn(r);
    h = *(ushort_t*)&bh;
    l = *(ushort_t*)&bl;
}
__device__ __forceinline__ void splitpack(float x0, float x1, unsigned& hh, unsigned& ll) {
    ushort_t h0, l0, h1, l1;
    split2(x0, h0, l0);
    split2(x1, h1, l1);
    hh = (unsigned)h0 | ((unsigned)h1 << 16);
    ll = (unsigned)l0 | ((unsigned)l1 << 16);
}
__device__ __forceinline__ void mma16816(float c[4], const unsigned a[4], const unsigned b[2]) {
    asm volatile(
        "mma.sync.aligned.m16n8k16.row.col.f32.bf16.bf16.f32 "
        "{%0,%1,%2,%3}, {%4,%5,%6,%7}, {%8,%9}, {%0,%1,%2,%3};\n"
        : "+f"(c[0]), "+f"(c[1]), "+f"(c[2]), "+f"(c[3])
        : "r"(a[0]), "r"(a[1]), "r"(a[2]), "r"(a[3]), "r"(b[0]), "r"(b[1]));
}
__device__ __forceinline__ void ldsm_x4(unsigned* r, uint32_t a) {
    asm volatile("ldmatrix.sync.aligned.m8n8.x4.shared.b16 {%0,%1,%2,%3}, [%4];"
                 : "=r"(r[0]), "=r"(r[1]), "=r"(r[2]), "=r"(r[3]) : "r"(a));
}

// Issue one stage's cp.async loads. A: 64 rows (1 row/thread), B: 128 rows (2 rows/thread).
__device__ __forceinline__ void stage_issue(
    uint32_t base, const ushort_t* Ah, const ushort_t* Al,
    const ushort_t* Bh, const ushort_t* Bl,
    size_t strideA, size_t strideB, int k0, int r0, int seg) {
    const uint32_t ro = (uint32_t)r0 * 80u + (uint32_t)seg * 2u;
    cpa16(base + ro,                             Ah + (size_t)r0 * strideA + k0 + seg);
    cpa16(base + SLAB_A + ro,                    Al + (size_t)r0 * strideA + k0 + seg);
    cpa16(base + 2*SLAB_A + ro,                  Bh + (size_t)r0 * strideB + k0 + seg);
    cpa16(base + 2*SLAB_A + ro + 5120u,          Bh + (size_t)(r0 + 64) * strideB + k0 + seg);
    cpa16(base + 2*SLAB_A + SLAB_B + ro,         Bl + (size_t)r0 * strideB + k0 + seg);
    cpa16(base + 2*SLAB_A + SLAB_B + ro + 5120u, Bl + (size_t)(r0 + 64) * strideB + k0 + seg);
    asm volatile("cp.async.commit_group;");
}

// One staged chunk: warp computes its 32x32 tile over k=32. Term-major mma order.
__device__ __forceinline__ void chunk_mma(uint32_t base, int lane, int wm, int wn,
                                          float c[2][4][4]) {
    const uint32_t aAddr = base + (uint32_t)(wm * 32 + (lane & 15)) * 80u + ((lane >> 4) * 8u) * 2u;
    const uint32_t bBase = base + 2*SLAB_A
                         + (uint32_t)((lane & 7) + (((lane >> 4) & 1) * 8)) * 80u
                         + (((lane >> 3) & 1) * 8u) * 2u;
#pragma unroll
    for (int kh = 0; kh < 2; kh++) {
        const uint32_t ko = kh * 32u;
        unsigned ah[2][4], al[2][4];
        ldsm_x4(ah[0], aAddr + ko);
        ldsm_x4(ah[1], aAddr + 1280u + ko);
        ldsm_x4(al[0], aAddr + SLAB_A + ko);
        ldsm_x4(al[1], aAddr + SLAB_A + 1280u + ko);
#pragma unroll
        for (int j = 0; j < 2; j++) {
            const uint32_t bj = bBase + (uint32_t)(wn * 32 + j * 16) * 80u + ko;
            unsigned bh4[4], bl4[4];
            ldsm_x4(bh4, bj);
            ldsm_x4(bl4, bj + SLAB_B);
            // term hi*hi (4 independent chains)
#pragma unroll
            for (int nn = 0; nn < 2; nn++) {
                unsigned b2[2] = {bh4[nn * 2], bh4[nn * 2 + 1]};
                mma16816(c[0][j * 2 + nn], ah[0], b2);
                mma16816(c[1][j * 2 + nn], ah[1], b2);
            }
            // term lo*hi
#pragma unroll
            for (int nn = 0; nn < 2; nn++) {
                unsigned b2[2] = {bh4[nn * 2], bh4[nn * 2 + 1]};
                mma16816(c[0][j * 2 + nn], al[0], b2);
                mma16816(c[1][j * 2 + nn], al[1], b2);
            }
            // term hi*lo
#pragma unroll
            for (int nn = 0; nn < 2; nn++) {
                unsigned b2[2] = {bl4[nn * 2], bl4[nn * 2 + 1]};
                mma16816(c[0][j * 2 + nn], ah[0], b2);
                mma16816(c[1][j * 2 + nn], ah[1], b2);
            }
        }
    }
}

// Pipelined tile GEMM over NC chunks of k=32. Two stages of dynamic smem.
__device__ __forceinline__ void tile_gemm(
    uint32_t sb, const ushort_t* Ah, const ushort_t* Al,
    const ushort_t* Bh, const ushort_t* Bl,
    size_t strideA, size_t strideB, int NC, int tid, float c[2][4][4]) {
    const int lane = tid & 31, wid = tid >> 5;
    const int wm = wid & 1, wn = wid >> 1;
    const int r0 = tid >> 2, seg = (tid & 3) * 8;

    stage_issue(sb, Ah, Al, Bh, Bl, strideA, strideB, 0, r0, seg);
    for (int kc = 0; kc < NC; kc++) {
        const int s = kc & 1;
        if (kc + 1 < NC) {
            stage_issue(sb + (uint32_t)(s ^ 1) * STAGE, Ah, Al, Bh, Bl,
                        strideA, strideB, (kc + 1) * 32, r0, seg);
            asm volatile("cp.async.wait_group 1;");
        } else {
            asm volatile("cp.async.wait_group 0;");
        }
        __syncthreads();
        chunk_mma(sb + (uint32_t)s * STAGE, lane, wm, wn, c);
        __syncthreads();
    }
}

// ---------------- kernel 0: zero -----------------------------------------------
__global__ void zero_kernel(float* __restrict__ out) {
    int i = blockIdx.x * blockDim.x + threadIdx.x;
    if (i < BATCH * SEQ * HEAD) out[i] = 0.0f;
    if (i < BATCH * SEQ) g_colsum[i] = 0.0f;
}

// ---------------- prep: split X ------------------------------------------------
__global__ __launch_bounds__(256) void prep_x(const float* __restrict__ X) {
    int p = blockIdx.x * 256 + threadIdx.x;
    int row = p >> 9, kp = (p & 511) * 2;
    float2 v = *(const float2*)(X + (size_t)row * EMB + kp);
    unsigned hh, ll;
    splitpack(v.x, v.y, hh, ll);
    *(unsigned*)&g_xh[(size_t)row * EMB + kp] = hh;
    *(unsigned*)&g_xl[(size_t)row * EMB + kp] = ll;
}

// ---------------- prep: split W^T ----------------------------------------------
__global__ __launch_bounds__(256) void prep_w(const float* __restrict__ Wq,
                                              const float* __restrict__ Wk,
                                              const float* __restrict__ Wv) {
    int p = blockIdx.x * 256 + threadIdx.x;
    int mat = p >> 16;
    int rem = p & 65535;
    int n = rem >> 9, kp = (rem & 511) * 2;
    const float* W = (mat == 0) ? Wq : (mat == 1) ? Wk : Wv;
    float v0 = W[(size_t)kp * HEAD + n];
    float v1 = W[(size_t)(kp + 1) * HEAD + n];
    unsigned hh, ll;
    splitpack(v0, v1, hh, ll);
    size_t off = (size_t)(mat * HEAD + n) * EMB + kp;
    *(unsigned*)&g_wth[off] = hh;
    *(unsigned*)&g_wtl[off] = ll;
}

// ---------------- kernel 1: QKV (M-tile 64) ------------------------------------
__global__ __launch_bounds__(256, 3) void qkv_tc(void) {
    extern __shared__ ushort_t dynS[];
    const int tid = threadIdx.x, lane = tid & 31, wid = tid >> 5;
    const int wm = wid & 1, wn = wid >> 1;
    const int rt = blockIdx.x, mat = blockIdx.y;
    const uint32_t sb = smem_u32(dynS);

    float c[2][4][4];
#pragma unroll
    for (int m = 0; m < 2; m++)
#pragma unroll
        for (int n = 0; n < 4; n++)
#pragma unroll
            for (int i = 0; i < 4; i++) c[m][n][i] = 0.0f;

    tile_gemm(sb,
              g_xh + (size_t)(rt * 64) * EMB, g_xl + (size_t)(rt * 64) * EMB,
              g_wth + (size_t)(mat * HEAD) * EMB, g_wtl + (size_t)(mat * HEAD) * EMB,
              EMB, EMB, 32, tid, c);

    const int gid = lane >> 2, tig = lane & 3;
    if (mat == 2) {
#pragma unroll
        for (int m = 0; m < 2; m++) {
            const int r = rt * 64 + wm * 32 + m * 16 + gid;
#pragma unroll
            for (int n = 0; n < 4; n++) {
                const int col = wn * 32 + n * 8 + tig * 2;
                *(float2*)(g_v + (size_t)r * HEAD + col)       = make_float2(c[m][n][0], c[m][n][1]);
                *(float2*)(g_v + (size_t)(r + 8) * HEAD + col) = make_float2(c[m][n][2], c[m][n][3]);
            }
        }
    } else {
        ushort_t* Yh = (mat == 0) ? g_qh : g_kh;
        ushort_t* Yl = (mat == 0) ? g_ql : g_kl;
        const float sc = (mat == 0) ? SCALE : 1.0f;
#pragma unroll
        for (int m = 0; m < 2; m++) {
            const int r = rt * 64 + wm * 32 + m * 16 + gid;
#pragma unroll
            for (int n = 0; n < 4; n++) {
                const int col = wn * 32 + n * 8 + tig * 2;
                unsigned hh, ll;
                splitpack(c[m][n][0] * sc, c[m][n][1] * sc, hh, ll);
                *(unsigned*)&Yh[(size_t)r * HEAD + col] = hh;
                *(unsigned*)&Yl[(size_t)r * HEAD + col] = ll;
                splitpack(c[m][n][2] * sc, c[m][n][3] * sc, hh, ll);
                *(unsigned*)&Yh[(size_t)(r + 8) * HEAD + col] = hh;
                *(unsigned*)&Yl[(size_t)(r + 8) * HEAD + col] = ll;
            }
        }
    }
}

// ---------------- kernel 2: scores (M-tile 64, q half-tiles) -------------------
__global__ __launch_bounds__(256, 3) void scores_tc(void) {
    extern __shared__ ushort_t dynS[];
    __shared__ float s_col[128];
    const int tid = threadIdx.x, lane = tid & 31, wid = tid >> 5;
    const int wm = wid & 1, wn = wid >> 1;
    const int b = blockIdx.x / (NTRI * 2);
    const int rem = blockIdx.x % (NTRI * 2);
    const int qsub = rem & 1;
    int qt, kt;
    tri_decode(rem >> 1, qt, kt);
    const uint32_t sb = smem_u32(dynS);

    if (tid < 128) s_col[tid] = 0.0f;

    float c[2][4][4];
#pragma unroll
    for (int m = 0; m < 2; m++)
#pragma unroll
        for (int n = 0; n < 4; n++)
#pragma unroll
            for (int i = 0; i < 4; i++) c[m][n][i] = 0.0f;

    tile_gemm(sb,
              g_qh + (size_t)(b * SEQ + qt * 128 + qsub * 64) * HEAD,
              g_ql + (size_t)(b * SEQ + qt * 128 + qsub * 64) * HEAD,
              g_kh + (size_t)(b * SEQ + kt * 128) * HEAD,
              g_kl + (size_t)(b * SEQ + kt * 128) * HEAD,
              HEAD, HEAD, 4, tid, c);

    const int gid = lane >> 2, tig = lane & 3;
    float p0[4], p1[4];
#pragma unroll
    for (int n = 0; n < 4; n++) { p0[n] = 0.0f; p1[n] = 0.0f; }

#pragma unroll
    for (int m = 0; m < 2; m++) {
        const int r   = wm * 32 + m * 16 + gid;
        const int gq0 = qt * 128 + qsub * 64 + r;
        const int gq1 = gq0 + 8;
#pragma unroll
        for (int n = 0; n < 4; n++) {
            const int cn = wn * 32 + n * 8 + tig * 2;
            const int gk = kt * 128 + cn;
            float e0 = (gq0 >= gk)     ? fast_exp(c[m][n][0]) : 0.0f;
            float e1 = (gq0 >= gk + 1) ? fast_exp(c[m][n][1]) : 0.0f;
            float e2 = (gq1 >= gk)     ? fast_exp(c[m][n][2]) : 0.0f;
            float e3 = (gq1 >= gk + 1) ? fast_exp(c[m][n][3]) : 0.0f;
            p0[n] += e0 + e2;
            p1[n] += e1 + e3;
            unsigned hh, ll;
            size_t base0 = ((size_t)b * SEQ + gq0) * SEQ + gk;
            splitpack(e0, e1, hh, ll);
            *(unsigned*)&g_eh[base0] = hh;
            *(unsigned*)&g_el[base0] = ll;
            size_t base1 = ((size_t)b * SEQ + gq1) * SEQ + gk;
            splitpack(e2, e3, hh, ll);
            *(unsigned*)&g_eh[base1] = hh;
            *(unsigned*)&g_el[base1] = ll;
        }
    }
#pragma unroll
    for (int n = 0; n < 4; n++) {
        p0[n] += __shfl_down_sync(0xffffffff, p0[n], 16);
        p0[n] += __shfl_down_sync(0xffffffff, p0[n], 8);
        p0[n] += __shfl_down_sync(0xffffffff, p0[n], 4);
        p1[n] += __shfl_down_sync(0xffffffff, p1[n], 16);
        p1[n] += __shfl_down_sync(0xffffffff, p1[n], 8);
        p1[n] += __shfl_down_sync(0xffffffff, p1[n], 4);
    }
    if (lane < 4) {
#pragma unroll
        for (int n = 0; n < 4; n++) {
            atomicAdd(&s_col[wn * 32 + n * 8 + lane * 2],     p0[n]);
            atomicAdd(&s_col[wn * 32 + n * 8 + lane * 2 + 1], p1[n]);
        }
    }
    __syncthreads();
    if (tid < 128) atomicAdd(&g_colsum[b * SEQ + kt * 128 + tid], s_col[tid]);
}

// ---------------- kernel 3: vprep — (v*inv)^T split ----------------------------
__global__ __launch_bounds__(256) void vprep_kernel() {
    __shared__ ushort_t sh[128][72], sl[128][72];
    const int tid   = threadIdx.x;
    const int batch = blockIdx.x >> 5;
    const int kt64  = blockIdx.x & 31;

    const int r  = tid >> 2;
    const int cb = (tid & 3) * 32;
    const int key = batch * SEQ + kt64 * 64 + r;
    const float inv = 1.0f / g_colsum[key];
    const float* vp = g_v + (size_t)key * HEAD + cb;
#pragma unroll
    for (int j = 0; j < 8; j++) {
        float4 v4 = *(const float4*)(vp + j * 4);
        float v[4] = {v4.x, v4.y, v4.z, v4.w};
#pragma unroll
        for (int i = 0; i < 4; i++) {
            ushort_t h, l;
            split2(v[i] * inv, h, l);
            sh[cb + j * 4 + i][r] = h;
            sl[cb + j * 4 + i][r] = l;
        }
    }
    __syncthreads();
    const int h  = tid >> 1;
    const int kc = (tid & 1) * 32;
    size_t gbase = (size_t)(batch * HEAD + h) * SEQ + kt64 * 64 + kc;
#pragma unroll
    for (int j = 0; j < 4; j++) {
        uint2 u0 = *(const uint2*)&sh[h][kc + j * 8];
        uint2 u1 = *(const uint2*)&sh[h][kc + j * 8 + 4];
        *(uint4*)&g_vth[gbase + j * 8] = make_uint4(u0.x, u0.y, u1.x, u1.y);
        uint2 w0 = *(const uint2*)&sl[h][kc + j * 8];
        uint2 w1 = *(const uint2*)&sl[h][kc + j * 8 + 4];
        *(uint4*)&g_vtl[gbase + j * 8] = make_uint4(w0.x, w0.y, w1.x, w1.y);
    }
}

// ---------------- kernel 4: out = expS' @ v' (M-tile 64) -----------------------
__global__ __launch_bounds__(256, 3) void out_tc(float* __restrict__ out) {
    extern __shared__ ushort_t dynS[];
    const int tid = threadIdx.x, lane = tid & 31, wid = tid >> 5;
    const int wm = wid & 1, wn = wid >> 1;
    const int b = blockIdx.x / (NTRI * 2);
    const int rem = blockIdx.x % (NTRI * 2);
    const int qsub = rem & 1;
    int qt, kt;
    tri_decode(rem >> 1, qt, kt);
    const uint32_t sb = smem_u32(dynS);

    float c[2][4][4];
#pragma unroll
    for (int m = 0; m < 2; m++)
#pragma unroll
        for (int n = 0; n < 4; n++)
#pragma unroll
            for (int i = 0; i < 4; i++) c[m][n][i] = 0.0f;

    tile_gemm(sb,
              g_eh + ((size_t)b * SEQ + qt * 128 + qsub * 64) * SEQ + kt * 128,
              g_el + ((size_t)b * SEQ + qt * 128 + qsub * 64) * SEQ + kt * 128,
              g_vth + (size_t)(b * HEAD) * SEQ + kt * 128,
              g_vtl + (size_t)(b * HEAD) * SEQ + kt * 128,
              SEQ, SEQ, 4, tid, c);

    const int gid = lane >> 2, tig = lane & 3;
#pragma unroll
    for (int m = 0; m < 2; m++) {
        const int r = qt * 128 + qsub * 64 + wm * 32 + m * 16 + gid;
#pragma unroll
        for (int n = 0; n < 4; n++) {
            const int cn = wn * 32 + n * 8 + tig * 2;
            float* op = out + ((size_t)b * SEQ + r) * HEAD + cn;
            atomicAdd(op,     c[m][n][0]);
            atomicAdd(op + 1, c[m][n][1]);
            atomicAdd(op + (size_t)8 * HEAD,     c[m][n][2]);
            atomicAdd(op + (size_t)8 * HEAD + 1, c[m][n][3]);
        }
    }
}

// ---------------- launch --------------------------------------------------------
extern "C" void kernel_launch(void* const* d_in, const int* in_sizes, int n_in,
                              void* d_out, int out_size) {
    const float* X  = (const float*)d_in[0];
    const float* Wq = (const float*)d_in[1];
    const float* Wk = (const float*)d_in[2];
    const float* Wv = (const float*)d_in[3];
    float* out = (float*)d_out;

    const int smem = 2 * STAGE;   // 61440
    cudaFuncSetAttribute(qkv_tc,    cudaFuncAttributeMaxDynamicSharedMemorySize, smem);
    cudaFuncSetAttribute(scores_tc, cudaFuncAttributeMaxDynamicSharedMemorySize, smem);
    cudaFuncSetAttribute(out_tc,    cudaFuncAttributeMaxDynamicSharedMemorySize, smem);

    zero_kernel<<<(BATCH * SEQ * HEAD + 255) / 256, 256>>>(out);
    prep_x<<<BATCH * SEQ * EMB / 2 / 256, 256>>>(X);
    prep_w<<<3 * HEAD * EMB / 2 / 256, 256>>>(Wq, Wk, Wv);
    qkv_tc<<<dim3(BATCH * SEQ / 64, 3), 256, smem>>>();
    scores_tc<<<BATCH * NTRI * 2, 256, smem>>>();
    vprep_kernel<<<BATCH * SEQ / 64, 256>>>();
    out_tc<<<BATCH * NTRI * 2, 256, smem>>>(out);
}